// round 13
// baseline (speedup 1.0000x reference)
#include <cuda_runtime.h>
#include <cuda_bf16.h>
#include <mma.h>
#include <cstdint>
#include <cstddef>

using namespace nvcuda;

#define N_NODES 100000
#define N_EDGES 3200000
#define D_IN    512
#define D_HID   256
#define D_OUT   64

#define SCAN_BLK   512
#define SCAN_ITEMS 8
#define SCAN_TILE  (SCAN_BLK * SCAN_ITEMS)                 // 4096
#define SCAN_NB    ((N_NODES + SCAN_TILE - 1) / SCAN_TILE) // 25

// ---------------------------------------------------------------------------
// Scratch (allocation-free rule: __device__ globals)
// ---------------------------------------------------------------------------
__device__ float g_support1[(size_t)N_NODES * D_HID];  // x @ w1
__device__ float g_agg1[(size_t)N_NODES * D_HID];      // relu(spmm1 + b1)
__device__ float g_support2[(size_t)N_NODES * D_OUT];  // agg1 @ w2
__device__ int   g_cnt[N_NODES];
__device__ int   g_off[N_NODES];
__device__ int   g_ptr[N_NODES];
__device__ int   g_bsum[SCAN_NB];
__device__ int   g_ecol[N_EDGES];
__device__ float g_eew[N_EDGES];
// bf16 hi/lo split weights, [K][N] row-major (matches wmma row_major matrix_b)
__device__ __nv_bfloat16 g_w1hi[(size_t)D_IN * D_HID];
__device__ __nv_bfloat16 g_w1lo[(size_t)D_IN * D_HID];
__device__ __nv_bfloat16 g_w2hi[(size_t)D_HID * D_OUT];
__device__ __nv_bfloat16 g_w2lo[(size_t)D_HID * D_OUT];

// ---------------------------------------------------------------------------
// WMMA bf16 GEMM with 2-term split compensation (fp32-grade to ~1e-5):
//   C[M, N_DIM] = A[M, K_DIM] @ B[K_DIM, N_DIM]
//   B supplied pre-split as bf16 hi/lo. A split on the fly during smem stage.
// BM=128, BK=32, 8 warps (2 M x 4 N), warp tile 64 x (BN/4), 16x16x16 frags.
// Per fragment-pair: acc += Ahi*Bhi + Ahi*Blo + Alo*Bhi  (lo*lo ~2^-34 dropped)
// ---------------------------------------------------------------------------
template <int K_DIM, int N_DIM, int BN>
__global__ __launch_bounds__(256, 2)
void gemm_wmma(const float* __restrict__ A,
               const __nv_bfloat16* __restrict__ Bhi,
               const __nv_bfloat16* __restrict__ Blo,
               float* __restrict__ C, int M)
{
    constexpr int BM = 128, BK = 32;
    constexpr int AP = BK + 8;        // padded A row (halves): 80B, 16B-aligned
    constexpr int BP = BN + 8;        // padded B row (halves)
    constexpr int NF = BN / 64;       // wmma n-frags per warp (warp_n = BN/4)

    __shared__ __nv_bfloat16 As_hi[BM * AP], As_lo[BM * AP];
    __shared__ __nv_bfloat16 Bs_hi[BK * BP], Bs_lo[BK * BP];

    const int tid     = threadIdx.x;
    const int w       = tid >> 5;
    const int warp_m0 = (w & 1) * 64;
    const int warp_n0 = (w >> 1) * (BN / 4);
    const int row0    = blockIdx.y * BM;
    const int col0    = blockIdx.x * BN;

    wmma::fragment<wmma::accumulator, 16, 16, 16, float> acc[4][NF];
#pragma unroll
    for (int i = 0; i < 4; i++)
#pragma unroll
        for (int j = 0; j < NF; j++) wmma::fill_fragment(acc[i][j], 0.f);

    for (int k0 = 0; k0 < K_DIM; k0 += BK) {
        // ---- A tile: 128x32 fp32 -> bf16 hi/lo (4 float4 per thread) ----
#pragma unroll
        for (int t = 0; t < 4; t++) {
            int idx = tid + t * 256;          // 1024 float4 slots
            int r   = idx >> 3;
            int c4  = (idx & 7) << 2;
            float4 v = make_float4(0.f, 0.f, 0.f, 0.f);
            if (row0 + r < M)
                v = *reinterpret_cast<const float4*>(
                    A + (size_t)(row0 + r) * K_DIM + k0 + c4);
            __nv_bfloat16 hx = __float2bfloat16_rn(v.x);
            __nv_bfloat16 hy = __float2bfloat16_rn(v.y);
            __nv_bfloat16 hz = __float2bfloat16_rn(v.z);
            __nv_bfloat16 hw = __float2bfloat16_rn(v.w);
            int o = r * AP + c4;
            As_hi[o + 0] = hx; As_hi[o + 1] = hy;
            As_hi[o + 2] = hz; As_hi[o + 3] = hw;
            As_lo[o + 0] = __float2bfloat16_rn(v.x - __bfloat162float(hx));
            As_lo[o + 1] = __float2bfloat16_rn(v.y - __bfloat162float(hy));
            As_lo[o + 2] = __float2bfloat16_rn(v.z - __bfloat162float(hz));
            As_lo[o + 3] = __float2bfloat16_rn(v.w - __bfloat162float(hw));
        }
        // ---- B tiles: BKxBN bf16 hi/lo, uint4 (8 halves) per slot ----
#pragma unroll
        for (int idx = tid; idx < BK * BN / 8; idx += 256) {
            int r  = idx / (BN / 8);
            int c8 = (idx % (BN / 8)) * 8;
            size_t go = (size_t)(k0 + r) * N_DIM + col0 + c8;
            int    so = r * BP + c8;
            *reinterpret_cast<uint4*>(&Bs_hi[so]) =
                *reinterpret_cast<const uint4*>(&Bhi[go]);
            *reinterpret_cast<uint4*>(&Bs_lo[so]) =
                *reinterpret_cast<const uint4*>(&Blo[go]);
        }
        __syncthreads();

#pragma unroll
        for (int ks = 0; ks < BK; ks += 16) {
            wmma::fragment<wmma::matrix_b, 16, 16, 16, __nv_bfloat16,
                           wmma::row_major> bh[NF], bl[NF];
#pragma unroll
            for (int j = 0; j < NF; j++) {
                wmma::load_matrix_sync(bh[j], &Bs_hi[ks * BP + warp_n0 + j * 16], BP);
                wmma::load_matrix_sync(bl[j], &Bs_lo[ks * BP + warp_n0 + j * 16], BP);
            }
#pragma unroll
            for (int i = 0; i < 4; i++) {
                wmma::fragment<wmma::matrix_a, 16, 16, 16, __nv_bfloat16,
                               wmma::row_major> ah, al;
                wmma::load_matrix_sync(ah, &As_hi[(warp_m0 + i * 16) * AP + ks], AP);
                wmma::load_matrix_sync(al, &As_lo[(warp_m0 + i * 16) * AP + ks], AP);
#pragma unroll
                for (int j = 0; j < NF; j++) {
                    wmma::mma_sync(acc[i][j], ah, bh[j], acc[i][j]);
                    wmma::mma_sync(acc[i][j], ah, bl[j], acc[i][j]);
                    wmma::mma_sync(acc[i][j], al, bh[j], acc[i][j]);
                }
            }
        }
        __syncthreads();
    }

    // M % 16 == 0, so each 16-row fragment is fully in or fully out of range.
#pragma unroll
    for (int i = 0; i < 4; i++) {
        int gr = row0 + warp_m0 + i * 16;
        if (gr < M) {
#pragma unroll
            for (int j = 0; j < NF; j++)
                wmma::store_matrix_sync(
                    C + (size_t)gr * N_DIM + col0 + warp_n0 + j * 16,
                    acc[i][j], N_DIM, wmma::mem_row_major);
        }
    }
}

// ---------------------------------------------------------------------------
// Elementwise bf16 hi/lo split of a weight matrix (no transpose needed).
// ---------------------------------------------------------------------------
__global__ void split_w(const float* __restrict__ W,
                        __nv_bfloat16* __restrict__ Hi,
                        __nv_bfloat16* __restrict__ Lo, int n)
{
    int i = blockIdx.x * 256 + threadIdx.x;
    if (i >= n) return;
    float v = W[i];
    __nv_bfloat16 h = __float2bfloat16_rn(v);
    Hi[i] = h;
    Lo[i] = __float2bfloat16_rn(v - __bfloat162float(h));
}

// ---------------------------------------------------------------------------
// CSR build kernels (unchanged from R7 winner)
// ---------------------------------------------------------------------------
__global__ void zero_counts()
{
    int i = blockIdx.x * blockDim.x + threadIdx.x;
    if (i < N_NODES) { g_cnt[i] = 0; g_off[i] = 0; }
}

__global__ void histogram(const int* __restrict__ row)
{
    int e = blockIdx.x * blockDim.x + threadIdx.x;
    if (e < N_EDGES) atomicAdd(&g_cnt[row[e]], 1);
}

__global__ __launch_bounds__(SCAN_BLK)
void scan_blocks()
{
    __shared__ int s[SCAN_BLK];
    int t = threadIdx.x;
    int base = blockIdx.x * SCAN_TILE + t * SCAN_ITEMS;

    int local[SCAN_ITEMS];
    int sum = 0;
#pragma unroll
    for (int i = 0; i < SCAN_ITEMS; i++) {
        int idx = base + i;
        int v = (idx < N_NODES) ? g_cnt[idx] : 0;
        local[i] = sum;
        sum += v;
    }
    s[t] = sum;
    __syncthreads();
    for (int off = 1; off < SCAN_BLK; off <<= 1) {
        int v = (t >= off) ? s[t - off] : 0;
        __syncthreads();
        s[t] += v;
        __syncthreads();
    }
    int prefix = (t > 0) ? s[t - 1] : 0;
#pragma unroll
    for (int i = 0; i < SCAN_ITEMS; i++) {
        int idx = base + i;
        if (idx < N_NODES) g_ptr[idx] = prefix + local[i];
    }
    if (t == SCAN_BLK - 1) g_bsum[blockIdx.x] = s[t];
}

__global__ void scan_sums()
{
    if (threadIdx.x == 0) {
        int acc = 0;
        for (int i = 0; i < SCAN_NB; i++) {
            int v = g_bsum[i];
            g_bsum[i] = acc;
            acc += v;
        }
    }
}

__global__ __launch_bounds__(SCAN_BLK)
void add_offsets()
{
    int add = g_bsum[blockIdx.x];
    int base = blockIdx.x * SCAN_TILE + threadIdx.x * SCAN_ITEMS;
#pragma unroll
    for (int i = 0; i < SCAN_ITEMS; i++) {
        int idx = base + i;
        if (idx < N_NODES) g_ptr[idx] += add;
    }
}

__global__ void fill_csr(const int* __restrict__ row, const int* __restrict__ col,
                         const float* __restrict__ ew)
{
    int e = blockIdx.x * blockDim.x + threadIdx.x;
    if (e >= N_EDGES) return;
    int r = row[e];
    int p = g_ptr[r] + atomicAdd(&g_off[r], 1);
    g_ecol[p] = col[e];
    g_eew[p]  = ew[e];
}

// ---------------------------------------------------------------------------
// SpMM layer 1 (CSR, no atomics): one warp per row; + b1, relu fused.
// ---------------------------------------------------------------------------
__global__ __launch_bounds__(256)
void spmm1_csr(const float* __restrict__ sup, const float* __restrict__ b1,
               float* __restrict__ agg)
{
    int r = (blockIdx.x * 256 + threadIdx.x) >> 5;
    if (r >= N_NODES) return;
    int lane = threadIdx.x & 31;
    int start = g_ptr[r];
    int n     = g_cnt[r];

    float4 a0 = make_float4(0.f, 0.f, 0.f, 0.f);
    float4 a1 = make_float4(0.f, 0.f, 0.f, 0.f);
    for (int i = 0; i < n; i++) {
        int   c = g_ecol[start + i];
        float w = g_eew[start + i];
        const float4* s = reinterpret_cast<const float4*>(sup + (size_t)c * D_HID);
        float4 v0 = s[lane];
        float4 v1 = s[lane + 32];
        a0.x = fmaf(w, v0.x, a0.x); a0.y = fmaf(w, v0.y, a0.y);
        a0.z = fmaf(w, v0.z, a0.z); a0.w = fmaf(w, v0.w, a0.w);
        a1.x = fmaf(w, v1.x, a1.x); a1.y = fmaf(w, v1.y, a1.y);
        a1.z = fmaf(w, v1.z, a1.z); a1.w = fmaf(w, v1.w, a1.w);
    }
    const float4* bb = reinterpret_cast<const float4*>(b1);
    float4 bv0 = bb[lane], bv1 = bb[lane + 32];
    a0.x = fmaxf(a0.x + bv0.x, 0.f); a0.y = fmaxf(a0.y + bv0.y, 0.f);
    a0.z = fmaxf(a0.z + bv0.z, 0.f); a0.w = fmaxf(a0.w + bv0.w, 0.f);
    a1.x = fmaxf(a1.x + bv1.x, 0.f); a1.y = fmaxf(a1.y + bv1.y, 0.f);
    a1.z = fmaxf(a1.z + bv1.z, 0.f); a1.w = fmaxf(a1.w + bv1.w, 0.f);

    float4* dst = reinterpret_cast<float4*>(agg + (size_t)r * D_HID);
    dst[lane]      = a0;
    dst[lane + 32] = a1;
}

// ---------------------------------------------------------------------------
// SpMM layer 2 (CSR) + bias + log_softmax fused: one warp per row.
// ---------------------------------------------------------------------------
__global__ __launch_bounds__(256)
void spmm2_lsm(const float* __restrict__ sup, const float* __restrict__ b2,
               float* __restrict__ out)
{
    int r = (blockIdx.x * 256 + threadIdx.x) >> 5;
    if (r >= N_NODES) return;
    int lane = threadIdx.x & 31;
    int start = g_ptr[r];
    int n     = g_cnt[r];

    float2 a = make_float2(0.f, 0.f);
    for (int i = 0; i < n; i++) {
        int   c = g_ecol[start + i];
        float w = g_eew[start + i];
        float2 v = reinterpret_cast<const float2*>(sup + (size_t)c * D_OUT)[lane];
        a.x = fmaf(w, v.x, a.x);
        a.y = fmaf(w, v.y, a.y);
    }
    float2 bv = reinterpret_cast<const float2*>(b2)[lane];
    a.x += bv.x;
    a.y += bv.y;

    float m = fmaxf(a.x, a.y);
#pragma unroll
    for (int o = 16; o; o >>= 1) m = fmaxf(m, __shfl_xor_sync(0xffffffffu, m, o));
    float s = __expf(a.x - m) + __expf(a.y - m);
#pragma unroll
    for (int o = 16; o; o >>= 1) s += __shfl_xor_sync(0xffffffffu, s, o);
    float lse = m + logf(s);

    float2 res = make_float2(a.x - lse, a.y - lse);
    reinterpret_cast<float2*>(out + (size_t)r * D_OUT)[lane] = res;
}

// ---------------------------------------------------------------------------
extern "C" void kernel_launch(void* const* d_in, const int* in_sizes, int n_in,
                              void* d_out, int out_size)
{
    const float* x   = (const float*)d_in[0];
    const int*   row = (const int*)d_in[1];
    const int*   col = (const int*)d_in[2];
    const float* ew  = (const float*)d_in[3];
    const float* w1  = (const float*)d_in[4];
    const float* b1  = (const float*)d_in[5];
    const float* w2  = (const float*)d_in[6];
    const float* b2  = (const float*)d_in[7];
    float*       out = (float*)d_out;

    float *sup1, *agg1, *sup2;
    __nv_bfloat16 *w1hi, *w1lo, *w2hi, *w2lo;
    cudaGetSymbolAddress((void**)&sup1, g_support1);
    cudaGetSymbolAddress((void**)&agg1, g_agg1);
    cudaGetSymbolAddress((void**)&sup2, g_support2);
    cudaGetSymbolAddress((void**)&w1hi, g_w1hi);
    cudaGetSymbolAddress((void**)&w1lo, g_w1lo);
    cudaGetSymbolAddress((void**)&w2hi, g_w2hi);
    cudaGetSymbolAddress((void**)&w2lo, g_w2lo);

    // --- CSR build (reused by both layers) ---
    zero_counts<<<(N_NODES + 255) / 256, 256>>>();
    histogram<<<(N_EDGES + 255) / 256, 256>>>(row);
    scan_blocks<<<SCAN_NB, SCAN_BLK>>>();
    scan_sums<<<1, 32>>>();
    add_offsets<<<SCAN_NB, SCAN_BLK>>>();
    fill_csr<<<(N_EDGES + 255) / 256, 256>>>(row, col, ew);

    // --- Weight bf16 hi/lo split (row-major [K][N], no transpose) ---
    split_w<<<(D_IN * D_HID + 255) / 256, 256>>>(w1, w1hi, w1lo, D_IN * D_HID);
    split_w<<<(D_HID * D_OUT + 255) / 256, 256>>>(w2, w2hi, w2lo, D_HID * D_OUT);

    const int MTILES = (N_NODES + 127) / 128;  // 782

    // --- Layer 1: support1 = x @ w1 (WMMA bf16, 3-pass compensated) ---
    gemm_wmma<D_IN, D_HID, 128><<<dim3(D_HID / 128, MTILES), 256>>>(
        x, w1hi, w1lo, sup1, N_NODES);
    // agg1 = relu(segment_sum(ew * sup1[col]) + b1)
    spmm1_csr<<<(N_NODES * 32 + 255) / 256, 256>>>(sup1, b1, agg1);

    // --- Layer 2: support2 = agg1 @ w2 (WMMA bf16, 3-pass compensated) ---
    gemm_wmma<D_HID, D_OUT, 64><<<dim3(1, MTILES), 256>>>(
        agg1, w2hi, w2lo, sup2, N_NODES);
    // out = log_softmax(segment_sum(ew * sup2[col]) + b2)
    spmm2_lsm<<<(N_NODES * 32 + 255) / 256, 256>>>(sup2, b2, out);
}

// round 14
// speedup vs baseline: 1.0011x; 1.0011x over previous
#include <cuda_runtime.h>
#include <cuda_bf16.h>
#include <mma.h>
#include <cstdint>
#include <cstddef>

using namespace nvcuda;

#define N_NODES 100000
#define N_EDGES 3200000
#define D_IN    512
#define D_HID   256
#define D_OUT   64

#define SCAN_BLK   512
#define SCAN_ITEMS 8
#define SCAN_TILE  (SCAN_BLK * SCAN_ITEMS)                 // 4096
#define SCAN_NB    ((N_NODES + SCAN_TILE - 1) / SCAN_TILE) // 25

// ---------------------------------------------------------------------------
// Scratch (allocation-free rule: __device__ globals)
// ---------------------------------------------------------------------------
__device__ float g_support1[(size_t)N_NODES * D_HID];  // x @ w1
__device__ float g_agg1[(size_t)N_NODES * D_HID];      // relu(spmm1 + b1)
__device__ float g_support2[(size_t)N_NODES * D_OUT];  // agg1 @ w2
__device__ int   g_cnt[N_NODES];
__device__ int   g_off[N_NODES];
__device__ int   g_ptr[N_NODES];
__device__ int   g_bsum[SCAN_NB];
__device__ int   g_ecol[N_EDGES];
__device__ float g_eew[N_EDGES];
// bf16 hi/lo split weights, [K][N] row-major (matches wmma row_major matrix_b)
__device__ __nv_bfloat16 g_w1hi[(size_t)D_IN * D_HID];
__device__ __nv_bfloat16 g_w1lo[(size_t)D_IN * D_HID];
__device__ __nv_bfloat16 g_w2hi[(size_t)D_HID * D_OUT];
__device__ __nv_bfloat16 g_w2lo[(size_t)D_HID * D_OUT];

// ---------------------------------------------------------------------------
// WMMA bf16 GEMM with 2-term split compensation (fp32-grade to ~1e-5):
//   C[M, N_DIM] = A[M, K_DIM] @ B[K_DIM, N_DIM]
//   B supplied pre-split as bf16 hi/lo. A split on the fly during smem stage.
// BM=128, BK=32, 8 warps (2 M x 4 N), warp tile 64 x (BN/4), 16x16x16 frags.
// Per fragment-pair: acc += Ahi*Bhi + Ahi*Blo + Alo*Bhi  (lo*lo ~2^-34 dropped)
// ---------------------------------------------------------------------------
template <int K_DIM, int N_DIM, int BN>
__global__ __launch_bounds__(256, 2)
void gemm_wmma(const float* __restrict__ A,
               const __nv_bfloat16* __restrict__ Bhi,
               const __nv_bfloat16* __restrict__ Blo,
               float* __restrict__ C, int M)
{
    constexpr int BM = 128, BK = 32;
    constexpr int AP = BK + 8;        // padded A row (halves): 80B, 16B-aligned
    constexpr int BP = BN + 8;        // padded B row (halves)
    constexpr int NF = BN / 64;       // wmma n-frags per warp (warp_n = BN/4)

    __shared__ __nv_bfloat16 As_hi[BM * AP], As_lo[BM * AP];
    __shared__ __nv_bfloat16 Bs_hi[BK * BP], Bs_lo[BK * BP];

    const int tid     = threadIdx.x;
    const int w       = tid >> 5;
    const int warp_m0 = (w & 1) * 64;
    const int warp_n0 = (w >> 1) * (BN / 4);
    const int row0    = blockIdx.y * BM;
    const int col0    = blockIdx.x * BN;

    wmma::fragment<wmma::accumulator, 16, 16, 16, float> acc[4][NF];
#pragma unroll
    for (int i = 0; i < 4; i++)
#pragma unroll
        for (int j = 0; j < NF; j++) wmma::fill_fragment(acc[i][j], 0.f);

    for (int k0 = 0; k0 < K_DIM; k0 += BK) {
        // ---- A tile: 128x32 fp32 -> bf16 hi/lo (4 float4 per thread) ----
#pragma unroll
        for (int t = 0; t < 4; t++) {
            int idx = tid + t * 256;          // 1024 float4 slots
            int r   = idx >> 3;
            int c4  = (idx & 7) << 2;
            float4 v = make_float4(0.f, 0.f, 0.f, 0.f);
            if (row0 + r < M)
                v = *reinterpret_cast<const float4*>(
                    A + (size_t)(row0 + r) * K_DIM + k0 + c4);
            __nv_bfloat16 hx = __float2bfloat16_rn(v.x);
            __nv_bfloat16 hy = __float2bfloat16_rn(v.y);
            __nv_bfloat16 hz = __float2bfloat16_rn(v.z);
            __nv_bfloat16 hw = __float2bfloat16_rn(v.w);
            int o = r * AP + c4;
            As_hi[o + 0] = hx; As_hi[o + 1] = hy;
            As_hi[o + 2] = hz; As_hi[o + 3] = hw;
            As_lo[o + 0] = __float2bfloat16_rn(v.x - __bfloat162float(hx));
            As_lo[o + 1] = __float2bfloat16_rn(v.y - __bfloat162float(hy));
            As_lo[o + 2] = __float2bfloat16_rn(v.z - __bfloat162float(hz));
            As_lo[o + 3] = __float2bfloat16_rn(v.w - __bfloat162float(hw));
        }
        // ---- B tiles: BKxBN bf16 hi/lo, uint4 (8 halves) per slot ----
#pragma unroll
        for (int idx = tid; idx < BK * BN / 8; idx += 256) {
            int r  = idx / (BN / 8);
            int c8 = (idx % (BN / 8)) * 8;
            size_t go = (size_t)(k0 + r) * N_DIM + col0 + c8;
            int    so = r * BP + c8;
            *reinterpret_cast<uint4*>(&Bs_hi[so]) =
                *reinterpret_cast<const uint4*>(&Bhi[go]);
            *reinterpret_cast<uint4*>(&Bs_lo[so]) =
                *reinterpret_cast<const uint4*>(&Blo[go]);
        }
        __syncthreads();

#pragma unroll
        for (int ks = 0; ks < BK; ks += 16) {
            wmma::fragment<wmma::matrix_b, 16, 16, 16, __nv_bfloat16,
                           wmma::row_major> bh[NF], bl[NF];
#pragma unroll
            for (int j = 0; j < NF; j++) {
                wmma::load_matrix_sync(bh[j], &Bs_hi[ks * BP + warp_n0 + j * 16], BP);
                wmma::load_matrix_sync(bl[j], &Bs_lo[ks * BP + warp_n0 + j * 16], BP);
            }
#pragma unroll
            for (int i = 0; i < 4; i++) {
                wmma::fragment<wmma::matrix_a, 16, 16, 16, __nv_bfloat16,
                               wmma::row_major> ah, al;
                wmma::load_matrix_sync(ah, &As_hi[(warp_m0 + i * 16) * AP + ks], AP);
                wmma::load_matrix_sync(al, &As_lo[(warp_m0 + i * 16) * AP + ks], AP);
#pragma unroll
                for (int j = 0; j < NF; j++) {
                    wmma::mma_sync(acc[i][j], ah, bh[j], acc[i][j]);
                    wmma::mma_sync(acc[i][j], ah, bl[j], acc[i][j]);
                    wmma::mma_sync(acc[i][j], al, bh[j], acc[i][j]);
                }
            }
        }
        __syncthreads();
    }

    // M % 16 == 0, so each 16-row fragment is fully in or fully out of range.
#pragma unroll
    for (int i = 0; i < 4; i++) {
        int gr = row0 + warp_m0 + i * 16;
        if (gr < M) {
#pragma unroll
            for (int j = 0; j < NF; j++)
                wmma::store_matrix_sync(
                    C + (size_t)gr * N_DIM + col0 + warp_n0 + j * 16,
                    acc[i][j], N_DIM, wmma::mem_row_major);
        }
    }
}

// ---------------------------------------------------------------------------
// Elementwise bf16 hi/lo split of a weight matrix (no transpose needed).
// ---------------------------------------------------------------------------
__global__ void split_w(const float* __restrict__ W,
                        __nv_bfloat16* __restrict__ Hi,
                        __nv_bfloat16* __restrict__ Lo, int n)
{
    int i = blockIdx.x * 256 + threadIdx.x;
    if (i >= n) return;
    float v = W[i];
    __nv_bfloat16 h = __float2bfloat16_rn(v);
    Hi[i] = h;
    Lo[i] = __float2bfloat16_rn(v - __bfloat162float(h));
}

// ---------------------------------------------------------------------------
// CSR build kernels (unchanged from R7 winner)
// ---------------------------------------------------------------------------
__global__ void zero_counts()
{
    int i = blockIdx.x * blockDim.x + threadIdx.x;
    if (i < N_NODES) { g_cnt[i] = 0; g_off[i] = 0; }
}

__global__ void histogram(const int* __restrict__ row)
{
    int e = blockIdx.x * blockDim.x + threadIdx.x;
    if (e < N_EDGES) atomicAdd(&g_cnt[row[e]], 1);
}

__global__ __launch_bounds__(SCAN_BLK)
void scan_blocks()
{
    __shared__ int s[SCAN_BLK];
    int t = threadIdx.x;
    int base = blockIdx.x * SCAN_TILE + t * SCAN_ITEMS;

    int local[SCAN_ITEMS];
    int sum = 0;
#pragma unroll
    for (int i = 0; i < SCAN_ITEMS; i++) {
        int idx = base + i;
        int v = (idx < N_NODES) ? g_cnt[idx] : 0;
        local[i] = sum;
        sum += v;
    }
    s[t] = sum;
    __syncthreads();
    for (int off = 1; off < SCAN_BLK; off <<= 1) {
        int v = (t >= off) ? s[t - off] : 0;
        __syncthreads();
        s[t] += v;
        __syncthreads();
    }
    int prefix = (t > 0) ? s[t - 1] : 0;
#pragma unroll
    for (int i = 0; i < SCAN_ITEMS; i++) {
        int idx = base + i;
        if (idx < N_NODES) g_ptr[idx] = prefix + local[i];
    }
    if (t == SCAN_BLK - 1) g_bsum[blockIdx.x] = s[t];
}

__global__ void scan_sums()
{
    if (threadIdx.x == 0) {
        int acc = 0;
        for (int i = 0; i < SCAN_NB; i++) {
            int v = g_bsum[i];
            g_bsum[i] = acc;
            acc += v;
        }
    }
}

__global__ __launch_bounds__(SCAN_BLK)
void add_offsets()
{
    int add = g_bsum[blockIdx.x];
    int base = blockIdx.x * SCAN_TILE + threadIdx.x * SCAN_ITEMS;
#pragma unroll
    for (int i = 0; i < SCAN_ITEMS; i++) {
        int idx = base + i;
        if (idx < N_NODES) g_ptr[idx] += add;
    }
}

__global__ void fill_csr(const int* __restrict__ row, const int* __restrict__ col,
                         const float* __restrict__ ew)
{
    int e = blockIdx.x * blockDim.x + threadIdx.x;
    if (e >= N_EDGES) return;
    int r = row[e];
    int p = g_ptr[r] + atomicAdd(&g_off[r], 1);
    g_ecol[p] = col[e];
    g_eew[p]  = ew[e];
}

// ---------------------------------------------------------------------------
// SpMM layer 1 (CSR, no atomics): one warp per row; + b1, relu fused.
// ---------------------------------------------------------------------------
__global__ __launch_bounds__(256)
void spmm1_csr(const float* __restrict__ sup, const float* __restrict__ b1,
               float* __restrict__ agg)
{
    int r = (blockIdx.x * 256 + threadIdx.x) >> 5;
    if (r >= N_NODES) return;
    int lane = threadIdx.x & 31;
    int start = g_ptr[r];
    int n     = g_cnt[r];

    float4 a0 = make_float4(0.f, 0.f, 0.f, 0.f);
    float4 a1 = make_float4(0.f, 0.f, 0.f, 0.f);
    for (int i = 0; i < n; i++) {
        int   c = g_ecol[start + i];
        float w = g_eew[start + i];
        const float4* s = reinterpret_cast<const float4*>(sup + (size_t)c * D_HID);
        float4 v0 = s[lane];
        float4 v1 = s[lane + 32];
        a0.x = fmaf(w, v0.x, a0.x); a0.y = fmaf(w, v0.y, a0.y);
        a0.z = fmaf(w, v0.z, a0.z); a0.w = fmaf(w, v0.w, a0.w);
        a1.x = fmaf(w, v1.x, a1.x); a1.y = fmaf(w, v1.y, a1.y);
        a1.z = fmaf(w, v1.z, a1.z); a1.w = fmaf(w, v1.w, a1.w);
    }
    const float4* bb = reinterpret_cast<const float4*>(b1);
    float4 bv0 = bb[lane], bv1 = bb[lane + 32];
    a0.x = fmaxf(a0.x + bv0.x, 0.f); a0.y = fmaxf(a0.y + bv0.y, 0.f);
    a0.z = fmaxf(a0.z + bv0.z, 0.f); a0.w = fmaxf(a0.w + bv0.w, 0.f);
    a1.x = fmaxf(a1.x + bv1.x, 0.f); a1.y = fmaxf(a1.y + bv1.y, 0.f);
    a1.z = fmaxf(a1.z + bv1.z, 0.f); a1.w = fmaxf(a1.w + bv1.w, 0.f);

    float4* dst = reinterpret_cast<float4*>(agg + (size_t)r * D_HID);
    dst[lane]      = a0;
    dst[lane + 32] = a1;
}

// ---------------------------------------------------------------------------
// SpMM layer 2 (CSR) + bias + log_softmax fused: one warp per row.
// ---------------------------------------------------------------------------
__global__ __launch_bounds__(256)
void spmm2_lsm(const float* __restrict__ sup, const float* __restrict__ b2,
               float* __restrict__ out)
{
    int r = (blockIdx.x * 256 + threadIdx.x) >> 5;
    if (r >= N_NODES) return;
    int lane = threadIdx.x & 31;
    int start = g_ptr[r];
    int n     = g_cnt[r];

    float2 a = make_float2(0.f, 0.f);
    for (int i = 0; i < n; i++) {
        int   c = g_ecol[start + i];
        float w = g_eew[start + i];
        float2 v = reinterpret_cast<const float2*>(sup + (size_t)c * D_OUT)[lane];
        a.x = fmaf(w, v.x, a.x);
        a.y = fmaf(w, v.y, a.y);
    }
    float2 bv = reinterpret_cast<const float2*>(b2)[lane];
    a.x += bv.x;
    a.y += bv.y;

    float m = fmaxf(a.x, a.y);
#pragma unroll
    for (int o = 16; o; o >>= 1) m = fmaxf(m, __shfl_xor_sync(0xffffffffu, m, o));
    float s = __expf(a.x - m) + __expf(a.y - m);
#pragma unroll
    for (int o = 16; o; o >>= 1) s += __shfl_xor_sync(0xffffffffu, s, o);
    float lse = m + logf(s);

    float2 res = make_float2(a.x - lse, a.y - lse);
    reinterpret_cast<float2*>(out + (size_t)r * D_OUT)[lane] = res;
}

// ---------------------------------------------------------------------------
extern "C" void kernel_launch(void* const* d_in, const int* in_sizes, int n_in,
                              void* d_out, int out_size)
{
    const float* x   = (const float*)d_in[0];
    const int*   row = (const int*)d_in[1];
    const int*   col = (const int*)d_in[2];
    const float* ew  = (const float*)d_in[3];
    const float* w1  = (const float*)d_in[4];
    const float* b1  = (const float*)d_in[5];
    const float* w2  = (const float*)d_in[6];
    const float* b2  = (const float*)d_in[7];
    float*       out = (float*)d_out;

    float *sup1, *agg1, *sup2;
    __nv_bfloat16 *w1hi, *w1lo, *w2hi, *w2lo;
    cudaGetSymbolAddress((void**)&sup1, g_support1);
    cudaGetSymbolAddress((void**)&agg1, g_agg1);
    cudaGetSymbolAddress((void**)&sup2, g_support2);
    cudaGetSymbolAddress((void**)&w1hi, g_w1hi);
    cudaGetSymbolAddress((void**)&w1lo, g_w1lo);
    cudaGetSymbolAddress((void**)&w2hi, g_w2hi);
    cudaGetSymbolAddress((void**)&w2lo, g_w2lo);

    // --- CSR build (reused by both layers) ---
    zero_counts<<<(N_NODES + 255) / 256, 256>>>();
    histogram<<<(N_EDGES + 255) / 256, 256>>>(row);
    scan_blocks<<<SCAN_NB, SCAN_BLK>>>();
    scan_sums<<<1, 32>>>();
    add_offsets<<<SCAN_NB, SCAN_BLK>>>();
    fill_csr<<<(N_EDGES + 255) / 256, 256>>>(row, col, ew);

    // --- Weight bf16 hi/lo split (row-major [K][N], no transpose) ---
    split_w<<<(D_IN * D_HID + 255) / 256, 256>>>(w1, w1hi, w1lo, D_IN * D_HID);
    split_w<<<(D_HID * D_OUT + 255) / 256, 256>>>(w2, w2hi, w2lo, D_HID * D_OUT);

    const int MTILES = (N_NODES + 127) / 128;  // 782

    // --- Layer 1: support1 = x @ w1 (WMMA bf16, 3-pass compensated) ---
    gemm_wmma<D_IN, D_HID, 128><<<dim3(D_HID / 128, MTILES), 256>>>(
        x, w1hi, w1lo, sup1, N_NODES);
    // agg1 = relu(segment_sum(ew * sup1[col]) + b1)
    spmm1_csr<<<(N_NODES * 32 + 255) / 256, 256>>>(sup1, b1, agg1);

    // --- Layer 2: support2 = agg1 @ w2 (WMMA bf16, 3-pass compensated) ---
    gemm_wmma<D_HID, D_OUT, 64><<<dim3(1, MTILES), 256>>>(
        agg1, w2hi, w2lo, sup2, N_NODES);
    // out = log_softmax(segment_sum(ew * sup2[col]) + b2)
    spmm2_lsm<<<(N_NODES * 32 + 255) / 256, 256>>>(sup2, b2, out);
}

// round 15
// speedup vs baseline: 1.0067x; 1.0056x over previous
#include <cuda_runtime.h>
#include <cuda_bf16.h>
#include <mma.h>
#include <cstdint>
#include <cstddef>

using namespace nvcuda;

#define N_NODES 100000
#define N_EDGES 3200000
#define D_IN    512
#define D_HID   256
#define D_OUT   64

#define SCAN_BLK   512
#define SCAN_ITEMS 8
#define SCAN_TILE  (SCAN_BLK * SCAN_ITEMS)                 // 4096
#define SCAN_NB    ((N_NODES + SCAN_TILE - 1) / SCAN_TILE) // 25

// ---------------------------------------------------------------------------
// Scratch (allocation-free rule: __device__ globals)
// ---------------------------------------------------------------------------
__device__ float g_support1[(size_t)N_NODES * D_HID];  // x @ w1
__device__ float g_agg1[(size_t)N_NODES * D_HID];      // relu(spmm1 + b1)
__device__ float g_support2[(size_t)N_NODES * D_OUT];  // agg1 @ w2
__device__ int   g_cnt[N_NODES];
__device__ int   g_off[N_NODES];
__device__ int   g_ptr[N_NODES];
__device__ int   g_bsum[SCAN_NB];
__device__ int   g_ecol[N_EDGES];
__device__ float g_eew[N_EDGES];
// bf16 hi/lo split weights, [K][N] row-major (matches wmma row_major matrix_b)
__device__ __nv_bfloat16 g_w1hi[(size_t)D_IN * D_HID];
__device__ __nv_bfloat16 g_w1lo[(size_t)D_IN * D_HID];
__device__ __nv_bfloat16 g_w2hi[(size_t)D_HID * D_OUT];
__device__ __nv_bfloat16 g_w2lo[(size_t)D_HID * D_OUT];

// ---------------------------------------------------------------------------
// WMMA bf16 GEMM with 2-term split compensation (fp32-grade to ~1e-5):
//   C[M, N_DIM] = A[M, K_DIM] @ B[K_DIM, N_DIM]
//   B supplied pre-split as bf16 hi/lo. A split on the fly during smem stage.
// BM=128, BK=32, 8 warps (2 M x 4 N), warp tile 64 x (BN/4), 16x16x16 frags.
// Per fragment-pair: acc += Ahi*Bhi + Ahi*Blo + Alo*Bhi  (lo*lo ~2^-34 dropped)
// ---------------------------------------------------------------------------
template <int K_DIM, int N_DIM, int BN>
__global__ __launch_bounds__(256, 2)
void gemm_wmma(const float* __restrict__ A,
               const __nv_bfloat16* __restrict__ Bhi,
               const __nv_bfloat16* __restrict__ Blo,
               float* __restrict__ C, int M)
{
    constexpr int BM = 128, BK = 32;
    constexpr int AP = BK + 8;        // padded A row (halves): 80B, 16B-aligned
    constexpr int BP = BN + 8;        // padded B row (halves)
    constexpr int NF = BN / 64;       // wmma n-frags per warp (warp_n = BN/4)

    __shared__ __nv_bfloat16 As_hi[BM * AP], As_lo[BM * AP];
    __shared__ __nv_bfloat16 Bs_hi[BK * BP], Bs_lo[BK * BP];

    const int tid     = threadIdx.x;
    const int w       = tid >> 5;
    const int warp_m0 = (w & 1) * 64;
    const int warp_n0 = (w >> 1) * (BN / 4);
    const int row0    = blockIdx.y * BM;
    const int col0    = blockIdx.x * BN;

    wmma::fragment<wmma::accumulator, 16, 16, 16, float> acc[4][NF];
#pragma unroll
    for (int i = 0; i < 4; i++)
#pragma unroll
        for (int j = 0; j < NF; j++) wmma::fill_fragment(acc[i][j], 0.f);

    for (int k0 = 0; k0 < K_DIM; k0 += BK) {
        // ---- A tile: 128x32 fp32 -> bf16 hi/lo (4 float4 per thread) ----
#pragma unroll
        for (int t = 0; t < 4; t++) {
            int idx = tid + t * 256;          // 1024 float4 slots
            int r   = idx >> 3;
            int c4  = (idx & 7) << 2;
            float4 v = make_float4(0.f, 0.f, 0.f, 0.f);
            if (row0 + r < M)
                v = *reinterpret_cast<const float4*>(
                    A + (size_t)(row0 + r) * K_DIM + k0 + c4);
            __nv_bfloat16 hx = __float2bfloat16_rn(v.x);
            __nv_bfloat16 hy = __float2bfloat16_rn(v.y);
            __nv_bfloat16 hz = __float2bfloat16_rn(v.z);
            __nv_bfloat16 hw = __float2bfloat16_rn(v.w);
            int o = r * AP + c4;
            As_hi[o + 0] = hx; As_hi[o + 1] = hy;
            As_hi[o + 2] = hz; As_hi[o + 3] = hw;
            As_lo[o + 0] = __float2bfloat16_rn(v.x - __bfloat162float(hx));
            As_lo[o + 1] = __float2bfloat16_rn(v.y - __bfloat162float(hy));
            As_lo[o + 2] = __float2bfloat16_rn(v.z - __bfloat162float(hz));
            As_lo[o + 3] = __float2bfloat16_rn(v.w - __bfloat162float(hw));
        }
        // ---- B tiles: BKxBN bf16 hi/lo, uint4 (8 halves) per slot ----
#pragma unroll
        for (int idx = tid; idx < BK * BN / 8; idx += 256) {
            int r  = idx / (BN / 8);
            int c8 = (idx % (BN / 8)) * 8;
            size_t go = (size_t)(k0 + r) * N_DIM + col0 + c8;
            int    so = r * BP + c8;
            *reinterpret_cast<uint4*>(&Bs_hi[so]) =
                *reinterpret_cast<const uint4*>(&Bhi[go]);
            *reinterpret_cast<uint4*>(&Bs_lo[so]) =
                *reinterpret_cast<const uint4*>(&Blo[go]);
        }
        __syncthreads();

#pragma unroll
        for (int ks = 0; ks < BK; ks += 16) {
            wmma::fragment<wmma::matrix_b, 16, 16, 16, __nv_bfloat16,
                           wmma::row_major> bh[NF], bl[NF];
#pragma unroll
            for (int j = 0; j < NF; j++) {
                wmma::load_matrix_sync(bh[j], &Bs_hi[ks * BP + warp_n0 + j * 16], BP);
                wmma::load_matrix_sync(bl[j], &Bs_lo[ks * BP + warp_n0 + j * 16], BP);
            }
#pragma unroll
            for (int i = 0; i < 4; i++) {
                wmma::fragment<wmma::matrix_a, 16, 16, 16, __nv_bfloat16,
                               wmma::row_major> ah, al;
                wmma::load_matrix_sync(ah, &As_hi[(warp_m0 + i * 16) * AP + ks], AP);
                wmma::load_matrix_sync(al, &As_lo[(warp_m0 + i * 16) * AP + ks], AP);
#pragma unroll
                for (int j = 0; j < NF; j++) {
                    wmma::mma_sync(acc[i][j], ah, bh[j], acc[i][j]);
                    wmma::mma_sync(acc[i][j], ah, bl[j], acc[i][j]);
                    wmma::mma_sync(acc[i][j], al, bh[j], acc[i][j]);
                }
            }
        }
        __syncthreads();
    }

    // M % 16 == 0, so each 16-row fragment is fully in or fully out of range.
#pragma unroll
    for (int i = 0; i < 4; i++) {
        int gr = row0 + warp_m0 + i * 16;
        if (gr < M) {
#pragma unroll
            for (int j = 0; j < NF; j++)
                wmma::store_matrix_sync(
                    C + (size_t)gr * N_DIM + col0 + warp_n0 + j * 16,
                    acc[i][j], N_DIM, wmma::mem_row_major);
        }
    }
}

// ---------------------------------------------------------------------------
// Elementwise bf16 hi/lo split of a weight matrix (no transpose needed).
// ---------------------------------------------------------------------------
__global__ void split_w(const float* __restrict__ W,
                        __nv_bfloat16* __restrict__ Hi,
                        __nv_bfloat16* __restrict__ Lo, int n)
{
    int i = blockIdx.x * 256 + threadIdx.x;
    if (i >= n) return;
    float v = W[i];
    __nv_bfloat16 h = __float2bfloat16_rn(v);
    Hi[i] = h;
    Lo[i] = __float2bfloat16_rn(v - __bfloat162float(h));
}

// ---------------------------------------------------------------------------
// CSR build kernels (unchanged from R7 winner)
// ---------------------------------------------------------------------------
__global__ void zero_counts()
{
    int i = blockIdx.x * blockDim.x + threadIdx.x;
    if (i < N_NODES) { g_cnt[i] = 0; g_off[i] = 0; }
}

__global__ void histogram(const int* __restrict__ row)
{
    int e = blockIdx.x * blockDim.x + threadIdx.x;
    if (e < N_EDGES) atomicAdd(&g_cnt[row[e]], 1);
}

__global__ __launch_bounds__(SCAN_BLK)
void scan_blocks()
{
    __shared__ int s[SCAN_BLK];
    int t = threadIdx.x;
    int base = blockIdx.x * SCAN_TILE + t * SCAN_ITEMS;

    int local[SCAN_ITEMS];
    int sum = 0;
#pragma unroll
    for (int i = 0; i < SCAN_ITEMS; i++) {
        int idx = base + i;
        int v = (idx < N_NODES) ? g_cnt[idx] : 0;
        local[i] = sum;
        sum += v;
    }
    s[t] = sum;
    __syncthreads();
    for (int off = 1; off < SCAN_BLK; off <<= 1) {
        int v = (t >= off) ? s[t - off] : 0;
        __syncthreads();
        s[t] += v;
        __syncthreads();
    }
    int prefix = (t > 0) ? s[t - 1] : 0;
#pragma unroll
    for (int i = 0; i < SCAN_ITEMS; i++) {
        int idx = base + i;
        if (idx < N_NODES) g_ptr[idx] = prefix + local[i];
    }
    if (t == SCAN_BLK - 1) g_bsum[blockIdx.x] = s[t];
}

__global__ void scan_sums()
{
    if (threadIdx.x == 0) {
        int acc = 0;
        for (int i = 0; i < SCAN_NB; i++) {
            int v = g_bsum[i];
            g_bsum[i] = acc;
            acc += v;
        }
    }
}

__global__ __launch_bounds__(SCAN_BLK)
void add_offsets()
{
    int add = g_bsum[blockIdx.x];
    int base = blockIdx.x * SCAN_TILE + threadIdx.x * SCAN_ITEMS;
#pragma unroll
    for (int i = 0; i < SCAN_ITEMS; i++) {
        int idx = base + i;
        if (idx < N_NODES) g_ptr[idx] += add;
    }
}

__global__ void fill_csr(const int* __restrict__ row, const int* __restrict__ col,
                         const float* __restrict__ ew)
{
    int e = blockIdx.x * blockDim.x + threadIdx.x;
    if (e >= N_EDGES) return;
    int r = row[e];
    int p = g_ptr[r] + atomicAdd(&g_off[r], 1);
    g_ecol[p] = col[e];
    g_eew[p]  = ew[e];
}

// ---------------------------------------------------------------------------
// SpMM layer 1 (CSR, no atomics): one warp per row; + b1, relu fused.
// ---------------------------------------------------------------------------
__global__ __launch_bounds__(256)
void spmm1_csr(const float* __restrict__ sup, const float* __restrict__ b1,
               float* __restrict__ agg)
{
    int r = (blockIdx.x * 256 + threadIdx.x) >> 5;
    if (r >= N_NODES) return;
    int lane = threadIdx.x & 31;
    int start = g_ptr[r];
    int n     = g_cnt[r];

    float4 a0 = make_float4(0.f, 0.f, 0.f, 0.f);
    float4 a1 = make_float4(0.f, 0.f, 0.f, 0.f);
    for (int i = 0; i < n; i++) {
        int   c = g_ecol[start + i];
        float w = g_eew[start + i];
        const float4* s = reinterpret_cast<const float4*>(sup + (size_t)c * D_HID);
        float4 v0 = s[lane];
        float4 v1 = s[lane + 32];
        a0.x = fmaf(w, v0.x, a0.x); a0.y = fmaf(w, v0.y, a0.y);
        a0.z = fmaf(w, v0.z, a0.z); a0.w = fmaf(w, v0.w, a0.w);
        a1.x = fmaf(w, v1.x, a1.x); a1.y = fmaf(w, v1.y, a1.y);
        a1.z = fmaf(w, v1.z, a1.z); a1.w = fmaf(w, v1.w, a1.w);
    }
    const float4* bb = reinterpret_cast<const float4*>(b1);
    float4 bv0 = bb[lane], bv1 = bb[lane + 32];
    a0.x = fmaxf(a0.x + bv0.x, 0.f); a0.y = fmaxf(a0.y + bv0.y, 0.f);
    a0.z = fmaxf(a0.z + bv0.z, 0.f); a0.w = fmaxf(a0.w + bv0.w, 0.f);
    a1.x = fmaxf(a1.x + bv1.x, 0.f); a1.y = fmaxf(a1.y + bv1.y, 0.f);
    a1.z = fmaxf(a1.z + bv1.z, 0.f); a1.w = fmaxf(a1.w + bv1.w, 0.f);

    float4* dst = reinterpret_cast<float4*>(agg + (size_t)r * D_HID);
    dst[lane]      = a0;
    dst[lane + 32] = a1;
}

// ---------------------------------------------------------------------------
// SpMM layer 2 (CSR) + bias + log_softmax fused: one warp per row.
// ---------------------------------------------------------------------------
__global__ __launch_bounds__(256)
void spmm2_lsm(const float* __restrict__ sup, const float* __restrict__ b2,
               float* __restrict__ out)
{
    int r = (blockIdx.x * 256 + threadIdx.x) >> 5;
    if (r >= N_NODES) return;
    int lane = threadIdx.x & 31;
    int start = g_ptr[r];
    int n     = g_cnt[r];

    float2 a = make_float2(0.f, 0.f);
    for (int i = 0; i < n; i++) {
        int   c = g_ecol[start + i];
        float w = g_eew[start + i];
        float2 v = reinterpret_cast<const float2*>(sup + (size_t)c * D_OUT)[lane];
        a.x = fmaf(w, v.x, a.x);
        a.y = fmaf(w, v.y, a.y);
    }
    float2 bv = reinterpret_cast<const float2*>(b2)[lane];
    a.x += bv.x;
    a.y += bv.y;

    float m = fmaxf(a.x, a.y);
#pragma unroll
    for (int o = 16; o; o >>= 1) m = fmaxf(m, __shfl_xor_sync(0xffffffffu, m, o));
    float s = __expf(a.x - m) + __expf(a.y - m);
#pragma unroll
    for (int o = 16; o; o >>= 1) s += __shfl_xor_sync(0xffffffffu, s, o);
    float lse = m + logf(s);

    float2 res = make_float2(a.x - lse, a.y - lse);
    reinterpret_cast<float2*>(out + (size_t)r * D_OUT)[lane] = res;
}

// ---------------------------------------------------------------------------
extern "C" void kernel_launch(void* const* d_in, const int* in_sizes, int n_in,
                              void* d_out, int out_size)
{
    const float* x   = (const float*)d_in[0];
    const int*   row = (const int*)d_in[1];
    const int*   col = (const int*)d_in[2];
    const float* ew  = (const float*)d_in[3];
    const float* w1  = (const float*)d_in[4];
    const float* b1  = (const float*)d_in[5];
    const float* w2  = (const float*)d_in[6];
    const float* b2  = (const float*)d_in[7];
    float*       out = (float*)d_out;

    float *sup1, *agg1, *sup2;
    __nv_bfloat16 *w1hi, *w1lo, *w2hi, *w2lo;
    cudaGetSymbolAddress((void**)&sup1, g_support1);
    cudaGetSymbolAddress((void**)&agg1, g_agg1);
    cudaGetSymbolAddress((void**)&sup2, g_support2);
    cudaGetSymbolAddress((void**)&w1hi, g_w1hi);
    cudaGetSymbolAddress((void**)&w1lo, g_w1lo);
    cudaGetSymbolAddress((void**)&w2hi, g_w2hi);
    cudaGetSymbolAddress((void**)&w2lo, g_w2lo);

    // --- CSR build (reused by both layers) ---
    zero_counts<<<(N_NODES + 255) / 256, 256>>>();
    histogram<<<(N_EDGES + 255) / 256, 256>>>(row);
    scan_blocks<<<SCAN_NB, SCAN_BLK>>>();
    scan_sums<<<1, 32>>>();
    add_offsets<<<SCAN_NB, SCAN_BLK>>>();
    fill_csr<<<(N_EDGES + 255) / 256, 256>>>(row, col, ew);

    // --- Weight bf16 hi/lo split (row-major [K][N], no transpose) ---
    split_w<<<(D_IN * D_HID + 255) / 256, 256>>>(w1, w1hi, w1lo, D_IN * D_HID);
    split_w<<<(D_HID * D_OUT + 255) / 256, 256>>>(w2, w2hi, w2lo, D_HID * D_OUT);

    const int MTILES = (N_NODES + 127) / 128;  // 782

    // --- Layer 1: support1 = x @ w1 (WMMA bf16, 3-pass compensated) ---
    gemm_wmma<D_IN, D_HID, 128><<<dim3(D_HID / 128, MTILES), 256>>>(
        x, w1hi, w1lo, sup1, N_NODES);
    // agg1 = relu(segment_sum(ew * sup1[col]) + b1)
    spmm1_csr<<<(N_NODES * 32 + 255) / 256, 256>>>(sup1, b1, agg1);

    // --- Layer 2: support2 = agg1 @ w2 (WMMA bf16, 3-pass compensated) ---
    gemm_wmma<D_HID, D_OUT, 64><<<dim3(1, MTILES), 256>>>(
        agg1, w2hi, w2lo, sup2, N_NODES);
    // out = log_softmax(segment_sum(ew * sup2[col]) + b2)
    spmm2_lsm<<<(N_NODES * 32 + 255) / 256, 256>>>(sup2, b2, out);
}

// round 16
// speedup vs baseline: 1.1021x; 1.0948x over previous
#include <cuda_runtime.h>
#include <cuda_bf16.h>
#include <mma.h>
#include <cstdint>
#include <cstddef>

using namespace nvcuda;

#define N_NODES 100000
#define N_EDGES 3200000
#define D_IN    512
#define D_HID   256
#define D_OUT   64

#define SCAN_BLK   512
#define SCAN_ITEMS 8
#define SCAN_TILE  (SCAN_BLK * SCAN_ITEMS)                 // 4096
#define SCAN_NB    ((N_NODES + SCAN_TILE - 1) / SCAN_TILE) // 25

// ---------------------------------------------------------------------------
// Scratch (allocation-free rule: __device__ globals)
// ---------------------------------------------------------------------------
__device__ float g_support1[(size_t)N_NODES * D_HID];  // x @ w1
__device__ float g_agg1[(size_t)N_NODES * D_HID];      // relu(spmm1 + b1)
__device__ float g_support2[(size_t)N_NODES * D_OUT];  // agg1 @ w2
__device__ int   g_cnt[N_NODES];
__device__ int   g_off[N_NODES];
__device__ int   g_ptr[N_NODES];
__device__ int   g_bsum[SCAN_NB];
__device__ int   g_ecol[N_EDGES];
__device__ float g_eew[N_EDGES];
// bf16 hi/lo split weights, [K][N] row-major (matches wmma row_major matrix_b)
__device__ __nv_bfloat16 g_w1hi[(size_t)D_IN * D_HID];
__device__ __nv_bfloat16 g_w1lo[(size_t)D_IN * D_HID];
__device__ __nv_bfloat16 g_w2hi[(size_t)D_HID * D_OUT];
__device__ __nv_bfloat16 g_w2lo[(size_t)D_HID * D_OUT];

__device__ __forceinline__ uint32_t cvta_smem_u32(const void* p) {
    uint32_t a;
    asm("{ .reg .u64 t; cvta.to.shared.u64 t, %1; cvt.u32.u64 %0, t; }"
        : "=r"(a) : "l"(p));
    return a;
}

__device__ __forceinline__ void cp_async16(void* s, const void* g) {
    uint32_t sa = cvta_smem_u32(s);
    asm volatile("cp.async.ca.shared.global [%0], [%1], 16;"
                 :: "r"(sa), "l"(g) : "memory");
}

// ---------------------------------------------------------------------------
// Pipelined WMMA bf16 GEMM with 2-term split compensation:
//   C[M, N_DIM] = A[M, K_DIM] @ B[K_DIM, N_DIM]
//   B pre-split bf16 hi/lo (cp.async, double-buffered smem).
//   A fp32, converted to bf16 hi/lo during smem stage (register prefetch).
// BM=128, BK=32, 8 warps (2 M x 4 N), 16x16x16 frags.
// acc += Ahi*Bhi + Ahi*Blo + Alo*Bhi  (lo*lo term ~2^-34, dropped)
// ---------------------------------------------------------------------------
template <int K_DIM, int N_DIM, int BN>
__global__ __launch_bounds__(256, 2)
void gemm_wmma(const float* __restrict__ A,
               const __nv_bfloat16* __restrict__ Bhi,
               const __nv_bfloat16* __restrict__ Blo,
               float* __restrict__ C, int M)
{
    constexpr int BM = 128, BK = 32;
    constexpr int AP = BK + 8;               // padded A row (halves)
    constexpr int BP = BN + 8;               // padded B row (halves)
    constexpr int NF = BN / 64;              // wmma n-frags per warp
    constexpr int NB = (BK * BN / 8) / 256;  // B uint4 slots per thread

    __shared__ __nv_bfloat16 As_hi[BM * AP], As_lo[BM * AP];
    __shared__ __nv_bfloat16 Bs_hi[2][BK * BP], Bs_lo[2][BK * BP];

    const int tid     = threadIdx.x;
    const int w       = tid >> 5;
    const int warp_m0 = (w & 1) * 64;
    const int warp_n0 = (w >> 1) * (BN / 4);
    const int row0    = blockIdx.y * BM;
    const int col0    = blockIdx.x * BN;

    wmma::fragment<wmma::accumulator, 16, 16, 16, float> acc[4][NF];
#pragma unroll
    for (int i = 0; i < 4; i++)
#pragma unroll
        for (int j = 0; j < NF; j++) wmma::fill_fragment(acc[i][j], 0.f);

    float4 aR[4];   // A register prefetch (one BK chunk)

    auto loadA = [&](int k0) {
#pragma unroll
        for (int t = 0; t < 4; t++) {
            int idx = tid + t * 256;
            int r   = idx >> 3;
            int c4  = (idx & 7) << 2;
            aR[t] = (row0 + r < M)
                ? *reinterpret_cast<const float4*>(
                      A + (size_t)(row0 + r) * K_DIM + k0 + c4)
                : make_float4(0.f, 0.f, 0.f, 0.f);
        }
    };
    auto issueB = [&](int k0, int buf) {
#pragma unroll
        for (int s = 0; s < NB; s++) {
            int idx = tid + s * 256;
            int r   = idx / (BN / 8);
            int c8  = (idx % (BN / 8)) * 8;
            size_t go = (size_t)(k0 + r) * N_DIM + col0 + c8;
            int    so = r * BP + c8;
            cp_async16(&Bs_hi[buf][so], Bhi + go);
            cp_async16(&Bs_lo[buf][so], Blo + go);
        }
        asm volatile("cp.async.commit_group;" ::: "memory");
    };
    auto storeA = [&]() {
#pragma unroll
        for (int t = 0; t < 4; t++) {
            int idx = tid + t * 256;
            int r   = idx >> 3;
            int c4  = (idx & 7) << 2;
            float4 v = aR[t];
            __nv_bfloat16 hx = __float2bfloat16_rn(v.x);
            __nv_bfloat16 hy = __float2bfloat16_rn(v.y);
            __nv_bfloat16 hz = __float2bfloat16_rn(v.z);
            __nv_bfloat16 hw = __float2bfloat16_rn(v.w);
            int o = r * AP + c4;
            *reinterpret_cast<__nv_bfloat162*>(&As_hi[o]) =
                __nv_bfloat162(hx, hy);
            *reinterpret_cast<__nv_bfloat162*>(&As_hi[o + 2]) =
                __nv_bfloat162(hz, hw);
            *reinterpret_cast<__nv_bfloat162*>(&As_lo[o]) = __nv_bfloat162(
                __float2bfloat16_rn(v.x - __bfloat162float(hx)),
                __float2bfloat16_rn(v.y - __bfloat162float(hy)));
            *reinterpret_cast<__nv_bfloat162*>(&As_lo[o + 2]) = __nv_bfloat162(
                __float2bfloat16_rn(v.z - __bfloat162float(hz)),
                __float2bfloat16_rn(v.w - __bfloat162float(hw)));
        }
    };

    loadA(0);
    issueB(0, 0);
    int buf = 0;

    for (int k0 = 0; k0 < K_DIM; k0 += BK) {
        storeA();
        const bool has_next = (k0 + BK < K_DIM);
        if (has_next) {
            loadA(k0 + BK);        // global LDGs issue early
            issueB(k0 + BK, buf ^ 1);
            asm volatile("cp.async.wait_group 1;" ::: "memory");
        } else {
            asm volatile("cp.async.wait_group 0;" ::: "memory");
        }
        __syncthreads();

#pragma unroll
        for (int ks = 0; ks < BK; ks += 16) {
            wmma::fragment<wmma::matrix_b, 16, 16, 16, __nv_bfloat16,
                           wmma::row_major> bh[NF], bl[NF];
#pragma unroll
            for (int j = 0; j < NF; j++) {
                wmma::load_matrix_sync(bh[j],
                    &Bs_hi[buf][ks * BP + warp_n0 + j * 16], BP);
                wmma::load_matrix_sync(bl[j],
                    &Bs_lo[buf][ks * BP + warp_n0 + j * 16], BP);
            }
#pragma unroll
            for (int i = 0; i < 4; i++) {
                wmma::fragment<wmma::matrix_a, 16, 16, 16, __nv_bfloat16,
                               wmma::row_major> ah, al;
                wmma::load_matrix_sync(ah, &As_hi[(warp_m0 + i * 16) * AP + ks], AP);
                wmma::load_matrix_sync(al, &As_lo[(warp_m0 + i * 16) * AP + ks], AP);
#pragma unroll
                for (int j = 0; j < NF; j++) {
                    wmma::mma_sync(acc[i][j], ah, bh[j], acc[i][j]);
                    wmma::mma_sync(acc[i][j], ah, bl[j], acc[i][j]);
                    wmma::mma_sync(acc[i][j], al, bh[j], acc[i][j]);
                }
            }
        }
        buf ^= 1;
        __syncthreads();
    }

    // M % 16 == 0: each 16-row fragment is fully in or fully out of range.
#pragma unroll
    for (int i = 0; i < 4; i++) {
        int gr = row0 + warp_m0 + i * 16;
        if (gr < M) {
#pragma unroll
            for (int j = 0; j < NF; j++)
                wmma::store_matrix_sync(
                    C + (size_t)gr * N_DIM + col0 + warp_n0 + j * 16,
                    acc[i][j], N_DIM, wmma::mem_row_major);
        }
    }
}

// ---------------------------------------------------------------------------
// Elementwise bf16 hi/lo split of a weight matrix.
// ---------------------------------------------------------------------------
__global__ void split_w(const float* __restrict__ W,
                        __nv_bfloat16* __restrict__ Hi,
                        __nv_bfloat16* __restrict__ Lo, int n)
{
    int i = blockIdx.x * 256 + threadIdx.x;
    if (i >= n) return;
    float v = W[i];
    __nv_bfloat16 h = __float2bfloat16_rn(v);
    Hi[i] = h;
    Lo[i] = __float2bfloat16_rn(v - __bfloat162float(h));
}

// ---------------------------------------------------------------------------
// CSR build kernels
// ---------------------------------------------------------------------------
__global__ void zero_counts()
{
    int i = blockIdx.x * blockDim.x + threadIdx.x;
    if (i < N_NODES) { g_cnt[i] = 0; g_off[i] = 0; }
}

__global__ void histogram(const int* __restrict__ row)
{
    int e = blockIdx.x * blockDim.x + threadIdx.x;
    if (e < N_EDGES) atomicAdd(&g_cnt[row[e]], 1);
}

__global__ __launch_bounds__(SCAN_BLK)
void scan_blocks()
{
    __shared__ int s[SCAN_BLK];
    int t = threadIdx.x;
    int base = blockIdx.x * SCAN_TILE + t * SCAN_ITEMS;

    int local[SCAN_ITEMS];
    int sum = 0;
#pragma unroll
    for (int i = 0; i < SCAN_ITEMS; i++) {
        int idx = base + i;
        int v = (idx < N_NODES) ? g_cnt[idx] : 0;
        local[i] = sum;
        sum += v;
    }
    s[t] = sum;
    __syncthreads();
    for (int off = 1; off < SCAN_BLK; off <<= 1) {
        int v = (t >= off) ? s[t - off] : 0;
        __syncthreads();
        s[t] += v;
        __syncthreads();
    }
    int prefix = (t > 0) ? s[t - 1] : 0;
#pragma unroll
    for (int i = 0; i < SCAN_ITEMS; i++) {
        int idx = base + i;
        if (idx < N_NODES) g_ptr[idx] = prefix + local[i];
    }
    if (t == SCAN_BLK - 1) g_bsum[blockIdx.x] = s[t];
}

__global__ void scan_sums()   // one warp, shfl scan over SCAN_NB block sums
{
    int t = threadIdx.x;
    int orig = (t < SCAN_NB) ? g_bsum[t] : 0;
    int v = orig;
#pragma unroll
    for (int o = 1; o < 32; o <<= 1) {
        int u = __shfl_up_sync(0xffffffffu, v, o);
        if (t >= o) v += u;
    }
    if (t < SCAN_NB) g_bsum[t] = v - orig;   // exclusive
}

__global__ __launch_bounds__(SCAN_BLK)
void add_offsets()
{
    int add = g_bsum[blockIdx.x];
    int base = blockIdx.x * SCAN_TILE + threadIdx.x * SCAN_ITEMS;
#pragma unroll
    for (int i = 0; i < SCAN_ITEMS; i++) {
        int idx = base + i;
        if (idx < N_NODES) g_ptr[idx] += add;
    }
}

__global__ void fill_csr(const int* __restrict__ row, const int* __restrict__ col,
                         const float* __restrict__ ew)
{
    int e = blockIdx.x * blockDim.x + threadIdx.x;
    if (e >= N_EDGES) return;
    int r = row[e];
    int p = g_ptr[r] + atomicAdd(&g_off[r], 1);
    g_ecol[p] = col[e];
    g_eew[p]  = ew[e];
}

// ---------------------------------------------------------------------------
// SpMM layer 1, column-blocked: one warp per row handles dims
// [COFF, COFF+128) (one float4 per lane). Launched twice -> hot gather set
// halves to 51 MB, fitting comfortably in L2. Bias + relu fused.
// ---------------------------------------------------------------------------
template <int COFF>
__global__ __launch_bounds__(256)
void spmm1_csr(const float* __restrict__ sup, const float* __restrict__ b1,
               float* __restrict__ agg)
{
    int r = (blockIdx.x * 256 + threadIdx.x) >> 5;
    if (r >= N_NODES) return;
    int lane  = threadIdx.x & 31;
    int start = g_ptr[r];
    int n     = g_cnt[r];
    int d     = COFF + lane * 4;

    float4 a = make_float4(0.f, 0.f, 0.f, 0.f);
    int i = 0;
    for (; i + 1 < n; i += 2) {              // 2x unroll for gather MLP
        int   c0 = g_ecol[start + i],     c1 = g_ecol[start + i + 1];
        float w0 = g_eew[start + i],      w1 = g_eew[start + i + 1];
        float4 v0 = *reinterpret_cast<const float4*>(sup + (size_t)c0 * D_HID + d);
        float4 v1 = *reinterpret_cast<const float4*>(sup + (size_t)c1 * D_HID + d);
        a.x = fmaf(w0, v0.x, a.x); a.y = fmaf(w0, v0.y, a.y);
        a.z = fmaf(w0, v0.z, a.z); a.w = fmaf(w0, v0.w, a.w);
        a.x = fmaf(w1, v1.x, a.x); a.y = fmaf(w1, v1.y, a.y);
        a.z = fmaf(w1, v1.z, a.z); a.w = fmaf(w1, v1.w, a.w);
    }
    if (i < n) {
        int   c = g_ecol[start + i];
        float w = g_eew[start + i];
        float4 v = *reinterpret_cast<const float4*>(sup + (size_t)c * D_HID + d);
        a.x = fmaf(w, v.x, a.x); a.y = fmaf(w, v.y, a.y);
        a.z = fmaf(w, v.z, a.z); a.w = fmaf(w, v.w, a.w);
    }
    float4 bv = *reinterpret_cast<const float4*>(b1 + d);
    a.x = fmaxf(a.x + bv.x, 0.f); a.y = fmaxf(a.y + bv.y, 0.f);
    a.z = fmaxf(a.z + bv.z, 0.f); a.w = fmaxf(a.w + bv.w, 0.f);
    *reinterpret_cast<float4*>(agg + (size_t)r * D_HID + d) = a;
}

// ---------------------------------------------------------------------------
// SpMM layer 2 (CSR) + bias + log_softmax fused: one warp per row.
// ---------------------------------------------------------------------------
__global__ __launch_bounds__(256)
void spmm2_lsm(const float* __restrict__ sup, const float* __restrict__ b2,
               float* __restrict__ out)
{
    int r = (blockIdx.x * 256 + threadIdx.x) >> 5;
    if (r >= N_NODES) return;
    int lane  = threadIdx.x & 31;
    int start = g_ptr[r];
    int n     = g_cnt[r];

    float2 a = make_float2(0.f, 0.f);
    int i = 0;
    for (; i + 1 < n; i += 2) {
        int   c0 = g_ecol[start + i],  c1 = g_ecol[start + i + 1];
        float w0 = g_eew[start + i],   w1 = g_eew[start + i + 1];
        float2 v0 = reinterpret_cast<const float2*>(sup + (size_t)c0 * D_OUT)[lane];
        float2 v1 = reinterpret_cast<const float2*>(sup + (size_t)c1 * D_OUT)[lane];
        a.x = fmaf(w0, v0.x, a.x); a.y = fmaf(w0, v0.y, a.y);
        a.x = fmaf(w1, v1.x, a.x); a.y = fmaf(w1, v1.y, a.y);
    }
    if (i < n) {
        int   c = g_ecol[start + i];
        float w = g_eew[start + i];
        float2 v = reinterpret_cast<const float2*>(sup + (size_t)c * D_OUT)[lane];
        a.x = fmaf(w, v.x, a.x);
        a.y = fmaf(w, v.y, a.y);
    }
    float2 bv = reinterpret_cast<const float2*>(b2)[lane];
    a.x += bv.x;
    a.y += bv.y;

    float m = fmaxf(a.x, a.y);
#pragma unroll
    for (int o = 16; o; o >>= 1) m = fmaxf(m, __shfl_xor_sync(0xffffffffu, m, o));
    float s = __expf(a.x - m) + __expf(a.y - m);
#pragma unroll
    for (int o = 16; o; o >>= 1) s += __shfl_xor_sync(0xffffffffu, s, o);
    float lse = m + logf(s);

    float2 res = make_float2(a.x - lse, a.y - lse);
    reinterpret_cast<float2*>(out + (size_t)r * D_OUT)[lane] = res;
}

// ---------------------------------------------------------------------------
extern "C" void kernel_launch(void* const* d_in, const int* in_sizes, int n_in,
                              void* d_out, int out_size)
{
    const float* x   = (const float*)d_in[0];
    const int*   row = (const int*)d_in[1];
    const int*   col = (const int*)d_in[2];
    const float* ew  = (const float*)d_in[3];
    const float* w1  = (const float*)d_in[4];
    const float* b1  = (const float*)d_in[5];
    const float* w2  = (const float*)d_in[6];
    const float* b2  = (const float*)d_in[7];
    float*       out = (float*)d_out;

    float *sup1, *agg1, *sup2;
    __nv_bfloat16 *w1hi, *w1lo, *w2hi, *w2lo;
    cudaGetSymbolAddress((void**)&sup1, g_support1);
    cudaGetSymbolAddress((void**)&agg1, g_agg1);
    cudaGetSymbolAddress((void**)&sup2, g_support2);
    cudaGetSymbolAddress((void**)&w1hi, g_w1hi);
    cudaGetSymbolAddress((void**)&w1lo, g_w1lo);
    cudaGetSymbolAddress((void**)&w2hi, g_w2hi);
    cudaGetSymbolAddress((void**)&w2lo, g_w2lo);

    const int MTILES = (N_NODES + 127) / 128;  // 782

    // Launch order puts GEMM1 at launch #4 — the ncu capture slot — so the
    // next profile shows the dominant kernel. Dependencies respected:
    // GEMM1 needs only split w1; CSR build is independent of the GEMMs.
    split_w<<<(D_IN * D_HID + 255) / 256, 256>>>(w1, w1hi, w1lo, D_IN * D_HID);   // 1
    split_w<<<(D_HID * D_OUT + 255) / 256, 256>>>(w2, w2hi, w2lo, D_HID * D_OUT); // 2
    zero_counts<<<(N_NODES + 255) / 256, 256>>>();                                 // 3
    gemm_wmma<D_IN, D_HID, 128><<<dim3(D_HID / 128, MTILES), 256>>>(               // 4
        x, w1hi, w1lo, sup1, N_NODES);

    // --- CSR build ---
    histogram<<<(N_EDGES + 255) / 256, 256>>>(row);
    scan_blocks<<<SCAN_NB, SCAN_BLK>>>();
    scan_sums<<<1, 32>>>();
    add_offsets<<<SCAN_NB, SCAN_BLK>>>();
    fill_csr<<<(N_EDGES + 255) / 256, 256>>>(row, col, ew);

    // agg1 = relu(segment_sum(ew * sup1[col]) + b1), column-blocked
    spmm1_csr<0><<<(N_NODES * 32 + 255) / 256, 256>>>(sup1, b1, agg1);
    spmm1_csr<128><<<(N_NODES * 32 + 255) / 256, 256>>>(sup1, b1, agg1);

    // --- Layer 2 ---
    gemm_wmma<D_HID, D_OUT, 64><<<dim3(1, MTILES), 256>>>(
        agg1, w2hi, w2lo, sup2, N_NODES);
    spmm2_lsm<<<(N_NODES * 32 + 255) / 256, 256>>>(sup2, b2, out);
}